// round 7
// baseline (speedup 1.0000x reference)
#include <cuda_runtime.h>
#include <cuda_bf16.h>
#include <stdint.h>

#define BATCH 4
#define NSEQ  4096
#define DDIM  1024
#define EDIM  1024

typedef __nv_bfloat16 bf16;

// ---------------- scratch (device globals; no allocations allowed) -------------
__device__ bf16 g_xh[(size_t)BATCH*NSEQ*DDIM], g_xl[(size_t)BATCH*NSEQ*DDIM];
__device__ bf16 g_yh[(size_t)BATCH*NSEQ*DDIM], g_yl[(size_t)BATCH*NSEQ*DDIM];
__device__ bf16 g_wqh[(size_t)EDIM*DDIM], g_wql[(size_t)EDIM*DDIM];
__device__ bf16 g_wkh[(size_t)EDIM*DDIM], g_wkl[(size_t)EDIM*DDIM];
__device__ bf16 g_wvh[(size_t)EDIM*DDIM], g_wvl[(size_t)EDIM*DDIM];
__device__ bf16 g_woh[(size_t)DDIM*EDIM], g_wol[(size_t)DDIM*EDIM];
__device__ bf16 g_qh[(size_t)BATCH*NSEQ*EDIM], g_ql[(size_t)BATCH*NSEQ*EDIM];
__device__ bf16 g_kh[(size_t)BATCH*NSEQ*EDIM], g_kl[(size_t)BATCH*NSEQ*EDIM];
__device__ bf16 g_vh[(size_t)BATCH*NSEQ*EDIM], g_vl[(size_t)BATCH*NSEQ*EDIM];
__device__ bf16 g_vth[(size_t)BATCH*EDIM*NSEQ], g_vtl[(size_t)BATCH*EDIM*NSEQ];
__device__ bf16 g_ph[(size_t)BATCH*NSEQ*NSEQ], g_pl[(size_t)BATCH*NSEQ*NSEQ];
__device__ bf16 g_ch[(size_t)BATCH*NSEQ*EDIM], g_cl[(size_t)BATCH*NSEQ*EDIM];
__device__ float g_spart[(size_t)BATCH*NSEQ*16];
__device__ float g_rinv[(size_t)BATCH*NSEQ];

// ---------------- helpers ----------------
__device__ __forceinline__ uint32_t smem_u32(const void* p) {
    uint32_t a;
    asm("{ .reg .u64 t; cvta.to.shared.u64 t, %1; cvt.u32.u64 %0, t; }" : "=r"(a) : "l"(p));
    return a;
}
__device__ __forceinline__ void cpa16(uint32_t dst, const void* src) {
    asm volatile("cp.async.cg.shared.global [%0], [%1], 16;" :: "r"(dst), "l"(src));
}

#define MMA_BF16(c, a, b) \
    asm volatile("mma.sync.aligned.m16n8k16.row.col.f32.bf16.bf16.f32 " \
                 "{%0,%1,%2,%3},{%4,%5,%6,%7},{%8,%9},{%0,%1,%2,%3};\n" \
                 : "+f"(c[0]), "+f"(c[1]), "+f"(c[2]), "+f"(c[3]) \
                 : "r"(a[0]), "r"(a[1]), "r"(a[2]), "r"(a[3]), "r"(b[0]), "r"(b[1]))

// ---------------- fp32 -> bf16 hi/lo split (batched over z) ----------------
__device__ __forceinline__ void split_one(const float4* src, bf16* hi, bf16* lo, int i)
{
    float4 v = src[i];
    float vs[4] = {v.x, v.y, v.z, v.w};
    bf16 h[4], l[4];
#pragma unroll
    for (int j = 0; j < 4; j++) {
        h[j] = __float2bfloat16(vs[j]);
        l[j] = __float2bfloat16(vs[j] - __bfloat162float(h[j]));
    }
    __nv_bfloat162 h01; h01.x = h[0]; h01.y = h[1];
    __nv_bfloat162 h23; h23.x = h[2]; h23.y = h[3];
    __nv_bfloat162 l01; l01.x = l[0]; l01.y = l[1];
    __nv_bfloat162 l23; l23.x = l[2]; l23.y = l[3];
    reinterpret_cast<__nv_bfloat162*>(hi)[2*i]   = h01;
    reinterpret_cast<__nv_bfloat162*>(hi)[2*i+1] = h23;
    reinterpret_cast<__nv_bfloat162*>(lo)[2*i]   = l01;
    reinterpret_cast<__nv_bfloat162*>(lo)[2*i+1] = l23;
}

__global__ void split_xy(const float4* __restrict__ x, bf16* xh, bf16* xl,
                         const float4* __restrict__ y, bf16* yh, bf16* yl, int n4)
{
    int i = blockIdx.x * blockDim.x + threadIdx.x;
    if (i >= n4) return;
    if (blockIdx.z == 0) split_one(x, xh, xl, i);
    else                 split_one(y, yh, yl, i);
}

__global__ void split_w(const float4* __restrict__ wq, bf16* wqh, bf16* wql,
                        const float4* __restrict__ wk, bf16* wkh, bf16* wkl,
                        const float4* __restrict__ wv, bf16* wvh, bf16* wvl,
                        const float4* __restrict__ wo, bf16* woh, bf16* wol, int n4)
{
    int i = blockIdx.x * blockDim.x + threadIdx.x;
    if (i >= n4) return;
    switch (blockIdx.z) {
        case 0: split_one(wq, wqh, wql, i); break;
        case 1: split_one(wk, wkh, wkl, i); break;
        case 2: split_one(wv, wvh, wvl, i); break;
        default: split_one(wo, woh, wol, i); break;
    }
}

// ---------------- bf16 transpose per batch: in [NSEQ, EDIM] -> out [EDIM, NSEQ] ---
__global__ __launch_bounds__(256)
void transpose_k(const bf16* __restrict__ in, bf16* __restrict__ out,
                 const bf16* __restrict__ in2, bf16* __restrict__ out2)
{
    __shared__ bf16 t[64][72];
    const int z = blockIdx.z & 3;
    const bf16* src = (blockIdx.z < 4) ? in : in2;
    bf16* dst       = (blockIdx.z < 4) ? out : out2;
    src += (size_t)z * NSEQ * EDIM;
    dst += (size_t)z * EDIM * NSEQ;
    const int x0 = blockIdx.x * 64;
    const int y0 = blockIdx.y * 64;
    const int tid = threadIdx.x;
    const int r = tid >> 3, c = (tid & 7) * 8;
#pragma unroll
    for (int i = 0; i < 2; i++) {
        uint4 v = *(const uint4*)(src + (size_t)(y0 + r + 32*i) * EDIM + x0 + c);
        *(uint4*)&t[r + 32*i][c] = v;
    }
    __syncthreads();
#pragma unroll
    for (int i = 0; i < 2; i++) {
        int orow = r + 32*i;
        bf16 tmp[8];
#pragma unroll
        for (int j = 0; j < 8; j++) tmp[j] = t[c + j][orow];
        *(uint4*)(dst + (size_t)(x0 + orow) * NSEQ + y0 + c) = *(uint4*)tmp;
    }
}

// ---------------- rowsum partials -> 1/sum ----------------
__global__ void rowsum_inv(const float* __restrict__ spart, float* __restrict__ rinv, int nrows)
{
    int r = blockIdx.x * 256 + threadIdx.x;
    if (r >= nrows) return;
    float s = 0.0f;
#pragma unroll
    for (int j = 0; j < 16; j++) s += spart[(size_t)r * 16 + j];
    rinv[r] = 1.0f / s;
}

// ---------------- HMMA split-bf16 GEMM, 512 threads, warp tile 32x64 ----------
// CTA tile 128 (M) x 256 (N), K_TILE=32, 3-stage cp.async.
// 16 warps: 4 along M (32 rows) x 4 along N (64 cols).
// OUT_MODE: 1 split hi/lo bf16; 2 fp32+bias; 3 exp/32 split + row partials; 4 *rinv split.

#define NSTAGE   3
#define MAT_A    (128 * 80)
#define MAT_BB   (256 * 80)
#define OFF_AL   (MAT_A)
#define OFF_BH   (2 * MAT_A)
#define STAGE_B  (2 * MAT_A + 2 * MAT_BB)
#define SMEM_B   (NSTAGE * STAGE_B)

template<int OUT_MODE>
__global__ __launch_bounds__(512, 1)
void gemm_hmma(const bf16* __restrict__ Ah, const bf16* __restrict__ Al,
               const bf16* __restrict__ Bh, const bf16* __restrict__ Bl,
               float* __restrict__ outF, bf16* __restrict__ outHi, bf16* __restrict__ outLo,
               const float* __restrict__ bias,
               float* __restrict__ spart, const float* __restrict__ rowscale,
               int M, int N, int K, long long sA, long long sB, long long sC)
{
    extern __shared__ __align__(16) char dsm[];
    __shared__ float part[128][4];
    const uint32_t sb = smem_u32(dsm);

    const int z = blockIdx.z;
    Ah += (size_t)z * sA;  Al += (size_t)z * sA;
    Bh += (size_t)z * sB;  Bl += (size_t)z * sB;

    const int tid = threadIdx.x;
    const int lane = tid & 31;
    const int warp = tid >> 5;
    const int m0 = blockIdx.y * 128;
    const int n0 = blockIdx.x * 256;

    const int wm0 = (warp & 3) * 32;          // 4 warps along M
    const int wn0 = (warp >> 2) * 64;         // 4 warps along N
    const int arow = lane & 15;
    const int acol = (lane >> 4) * 8;
    const int brow = lane & 7;
    const int bcol = ((lane >> 3) & 1) * 8;

    const int nk = K >> 5;

    const int ar = tid >> 2, ac = tid & 3;    // A: 1 chunk/thread/array

    auto load_stage = [&](int kt, int stg) {
        const uint32_t base = sb + stg * STAGE_B;
        const int kk = kt << 5;
        {
            uint32_t d = base + ar * 80 + ac * 16;
            const size_t g = (size_t)(m0 + ar) * K + kk + ac * 8;
            cpa16(d,          Ah + g);
            cpa16(d + OFF_AL, Al + g);
        }
#pragma unroll
        for (int i = 0; i < 2; i++) {
            const int id = tid + 512 * i;
            const int br = id >> 2, bc = id & 3;
            uint32_t d = base + OFF_BH + br * 80 + bc * 16;
            const size_t g = (size_t)(n0 + br) * K + kk + bc * 8;
            cpa16(d,           Bh + g);
            cpa16(d + MAT_BB,  Bl + g);
        }
        asm volatile("cp.async.commit_group;" ::: "memory");
    };

    float acc[2][8][4];
#pragma unroll
    for (int t = 0; t < 2; t++)
#pragma unroll
        for (int u = 0; u < 8; u++)
#pragma unroll
            for (int e = 0; e < 4; e++) acc[t][u][e] = 0.0f;

    load_stage(0, 0);
    load_stage(1, 1);

    for (int kt = 0; kt < nk; kt++) {
        asm volatile("cp.async.wait_group 1;" ::: "memory");
        __syncthreads();

        if (kt + 2 < nk) load_stage(kt + 2, (kt + 2) % NSTAGE);
        else             asm volatile("cp.async.commit_group;" ::: "memory");

        const uint32_t base = sb + (kt % NSTAGE) * STAGE_B;

#pragma unroll
        for (int ks = 0; ks < 2; ks++) {
            const int kbyte = ks * 32;
            uint32_t ah[2][4], al[2][4], bh[8][2], bl[8][2];
#pragma unroll
            for (int t = 0; t < 2; t++) {
                uint32_t ad = base + (uint32_t)(wm0 + t*16 + arow) * 80 + kbyte + acol * 2;
                asm volatile("ldmatrix.sync.aligned.m8n8.x4.shared.b16 {%0,%1,%2,%3}, [%4];\n"
                             : "=r"(ah[t][0]), "=r"(ah[t][1]), "=r"(ah[t][2]), "=r"(ah[t][3]) : "r"(ad));
                asm volatile("ldmatrix.sync.aligned.m8n8.x4.shared.b16 {%0,%1,%2,%3}, [%4];\n"
                             : "=r"(al[t][0]), "=r"(al[t][1]), "=r"(al[t][2]), "=r"(al[t][3]) : "r"(ad + OFF_AL));
            }
#pragma unroll
            for (int u = 0; u < 8; u++) {
                uint32_t bd = base + OFF_BH + (uint32_t)(wn0 + u*8 + brow) * 80 + kbyte + bcol * 2;
                asm volatile("ldmatrix.sync.aligned.m8n8.x2.shared.b16 {%0,%1}, [%2];\n"
                             : "=r"(bh[u][0]), "=r"(bh[u][1]) : "r"(bd));
                asm volatile("ldmatrix.sync.aligned.m8n8.x2.shared.b16 {%0,%1}, [%2];\n"
                             : "=r"(bl[u][0]), "=r"(bl[u][1]) : "r"(bd + MAT_BB));
            }
#pragma unroll
            for (int t = 0; t < 2; t++)
#pragma unroll
                for (int u = 0; u < 8; u++) MMA_BF16(acc[t][u], ah[t], bh[u]);
#pragma unroll
            for (int t = 0; t < 2; t++)
#pragma unroll
                for (int u = 0; u < 8; u++) MMA_BF16(acc[t][u], ah[t], bl[u]);
#pragma unroll
            for (int t = 0; t < 2; t++)
#pragma unroll
                for (int u = 0; u < 8; u++) MMA_BF16(acc[t][u], al[t], bh[u]);
        }
    }

    // ---- epilogue ----
    const size_t cbase = (size_t)z * sC;
#pragma unroll
    for (int t = 0; t < 2; t++) {
        const int gm = m0 + wm0 + t * 16 + (lane >> 2);
        float rs0 = 0.0f, rs1 = 0.0f;
        float rv0 = 1.0f, rv1 = 1.0f;
        if (OUT_MODE == 4) {
            rv0 = rowscale[(size_t)z * M + gm];
            rv1 = rowscale[(size_t)z * M + gm + 8];
        }
#pragma unroll
        for (int u = 0; u < 8; u++) {
            const int gn = n0 + wn0 + u * 8 + (lane & 3) * 2;
            float v00 = acc[t][u][0], v01 = acc[t][u][1];
            float v10 = acc[t][u][2], v11 = acc[t][u][3];
            if (OUT_MODE == 2) {
                float b0 = bias[gn], b1 = bias[gn + 1];
                v00 += b0; v01 += b1; v10 += b0; v11 += b1;
            }
            if (OUT_MODE == 3) {
                v00 = __expf(v00 * 0.03125f);
                v01 = __expf(v01 * 0.03125f);
                v10 = __expf(v10 * 0.03125f);
                v11 = __expf(v11 * 0.03125f);
                rs0 += v00 + v01;
                rs1 += v10 + v11;
            }
            if (OUT_MODE == 4) {
                v00 *= rv0; v01 *= rv0; v10 *= rv1; v11 *= rv1;
            }
            if (OUT_MODE == 2) {
                *(float2*)(outF + cbase + (size_t)gm * N + gn) = make_float2(v00, v01);
                *(float2*)(outF + cbase + (size_t)(gm + 8) * N + gn) = make_float2(v10, v11);
            } else {
                bf16 h00 = __float2bfloat16(v00), h01 = __float2bfloat16(v01);
                bf16 h10 = __float2bfloat16(v10), h11 = __float2bfloat16(v11);
                __nv_bfloat162 hp0; hp0.x = h00; hp0.y = h01;
                __nv_bfloat162 hp1; hp1.x = h10; hp1.y = h11;
                __nv_bfloat162 lp0; lp0.x = __float2bfloat16(v00 - __bfloat162float(h00));
                                    lp0.y = __float2bfloat16(v01 - __bfloat162float(h01));
                __nv_bfloat162 lp1; lp1.x = __float2bfloat16(v10 - __bfloat162float(h10));
                                    lp1.y = __float2bfloat16(v11 - __bfloat162float(h11));
                *(__nv_bfloat162*)(outHi + cbase + (size_t)gm * N + gn) = hp0;
                *(__nv_bfloat162*)(outHi + cbase + (size_t)(gm + 8) * N + gn) = hp1;
                *(__nv_bfloat162*)(outLo + cbase + (size_t)gm * N + gn) = lp0;
                *(__nv_bfloat162*)(outLo + cbase + (size_t)(gm + 8) * N + gn) = lp1;
            }
        }
        if (OUT_MODE == 3) {
            rs0 += __shfl_xor_sync(0xffffffffu, rs0, 1);
            rs0 += __shfl_xor_sync(0xffffffffu, rs0, 2);
            rs1 += __shfl_xor_sync(0xffffffffu, rs1, 1);
            rs1 += __shfl_xor_sync(0xffffffffu, rs1, 2);
            if ((lane & 3) == 0) {
                atomicAdd(&part[wm0 + t * 16 + (lane >> 2)][warp >> 2], 0.0f); // no-op keeps layout
            }
        }
    }
    if (OUT_MODE == 3) {
        // partial sums: 4 N-warp-groups per row; use smem, one writer per (row, group)
        __syncthreads();
        if (tid < 512) {
            // each warp writes its rows' partials (one lane per row pair did shfl)
        }
    }
    // NOTE: mode-3 partial path rewritten below via second pass
    if (OUT_MODE == 3) {
        // recompute per-thread row sums from acc and reduce via smem
        // (cheap: 64 FMAs) — row gm and gm+8 for t=0..1
        __syncthreads();
        if (tid == 0) { /* placeholder to keep structure */ }
    }
}

// ---- scores partial-sum: separate light kernel over E (reads Ph+Pl rows) -----
__global__ __launch_bounds__(256)
void rowsum_E(const bf16* __restrict__ Ph, const bf16* __restrict__ Pl,
              float* __restrict__ rinv)
{
    __shared__ float red[8];
    const size_t base = (size_t)blockIdx.x * NSEQ;
    const int tid = threadIdx.x;
    float s = 0.0f;
#pragma unroll
    for (int i = 0; i < NSEQ / (256 * 8); i++) {
        int idx = (i * 256 + tid) * 8;
        uint4 vh = *(const uint4*)(Ph + base + idx);
        uint4 vl = *(const uint4*)(Pl + base + idx);
        const __nv_bfloat162* hp = (const __nv_bfloat162*)&vh;
        const __nv_bfloat162* lp = (const __nv_bfloat162*)&vl;
#pragma unroll
        for (int j = 0; j < 4; j++) {
            float2 h2 = __bfloat1622float2(hp[j]);
            float2 l2 = __bfloat1622float2(lp[j]);
            s += h2.x + l2.x + h2.y + l2.y;
        }
    }
#pragma unroll
    for (int o = 16; o; o >>= 1) s += __shfl_xor_sync(0xffffffffu, s, o);
    if ((tid & 31) == 0) red[tid >> 5] = s;
    __syncthreads();
    if (tid == 0) {
        float t = 0.0f;
#pragma unroll
        for (int j = 0; j < 8; j++) t += red[j];
        rinv[blockIdx.x] = 1.0f / t;
    }
}

// ---------------- host ----------------
extern "C" void kernel_launch(void* const* d_in, const int* in_sizes, int n_in,
                              void* d_out, int out_size)
{
    const float* x  = (const float*)d_in[0];
    const float* y  = (const float*)d_in[1];
    const float* Wq = (const float*)d_in[2];
    const float* Wk = (const float*)d_in[3];
    const float* Wv = (const float*)d_in[4];
    const float* Wo = (const float*)d_in[5];
    const float* bo = (const float*)d_in[6];
    float* out = (float*)d_out;

#define GET(sym, var) void* var; cudaGetSymbolAddress(&var, sym)
    GET(g_xh, xh); GET(g_xl, xl); GET(g_yh, yh); GET(g_yl, yl);
    GET(g_wqh, wqh); GET(g_wql, wql); GET(g_wkh, wkh); GET(g_wkl, wkl);
    GET(g_wvh, wvh); GET(g_wvl, wvl); GET(g_woh, woh); GET(g_wol, wol);
    GET(g_qh, qh); GET(g_ql, ql); GET(g_kh, kh); GET(g_kl, kl);
    GET(g_vh, vh); GET(g_vl, vl); GET(g_vth, vth); GET(g_vtl, vtl);
    GET(g_ph, ph); GET(g_pl, pl); GET(g_ch, ch); GET(g_cl, cl);
    GET(g_rinv, rinv);
#undef GET

    cudaFuncSetAttribute(gemm_hmma<1>, cudaFuncAttributeMaxDynamicSharedMemorySize, SMEM_B);
    cudaFuncSetAttribute(gemm_hmma<2>, cudaFuncAttributeMaxDynamicSharedMemorySize, SMEM_B);
    cudaFuncSetAttribute(gemm_hmma<3>, cudaFuncAttributeMaxDynamicSharedMemorySize, SMEM_B);
    cudaFuncSetAttribute(gemm_hmma<4>, cudaFuncAttributeMaxDynamicSharedMemorySize, SMEM_B);

    const int MBN = BATCH * NSEQ;            // 16384

    // launches 0-1: splits (batched)
    {
        int n4 = BATCH * NSEQ * DDIM / 4;
        dim3 g1(n4 / 256, 1, 2);
        split_xy<<<g1, 256>>>((const float4*)x, (bf16*)xh, (bf16*)xl,
                              (const float4*)y, (bf16*)yh, (bf16*)yl, n4);
        int w4 = EDIM * DDIM / 4;
        dim3 g2(w4 / 256, 1, 4);
        split_w<<<g2, 256>>>((const float4*)Wq, (bf16*)wqh, (bf16*)wql,
                             (const float4*)Wk, (bf16*)wkh, (bf16*)wkl,
                             (const float4*)Wv, (bf16*)wvh, (bf16*)wvl,
                             (const float4*)Wo, (bf16*)woh, (bf16*)wol, w4);
    }

    // launches 2-4: projections
    {
        dim3 grid(EDIM / 256, MBN / 128, 1);
        gemm_hmma<1><<<grid, 512, SMEM_B>>>((bf16*)yh, (bf16*)yl, (bf16*)wqh, (bf16*)wql,
                                            nullptr, (bf16*)qh, (bf16*)ql, nullptr,
                                            nullptr, nullptr, MBN, EDIM, DDIM, 0, 0, 0);
        gemm_hmma<1><<<grid, 512, SMEM_B>>>((bf16*)xh, (bf16*)xl, (bf16*)wkh, (bf16*)wkl,
                                            nullptr, (bf16*)kh, (bf16*)kl, nullptr,
                                            nullptr, nullptr, MBN, EDIM, DDIM, 0, 0, 0);
        gemm_hmma<1><<<grid, 512, SMEM_B>>>((bf16*)xh, (bf16*)xl, (bf16*)wvh, (bf16*)wvl,
                                            nullptr, (bf16*)vh, (bf16*)vl, nullptr,
                                            nullptr, nullptr, MBN, EDIM, DDIM, 0, 0, 0);
    }

    // launch 5: scores+exp  (ncu -s 5 -c 1 profiles THIS)
    {
        dim3 grid(NSEQ / 256, NSEQ / 128, BATCH);
        gemm_hmma<3><<<grid, 512, SMEM_B>>>((bf16*)qh, (bf16*)ql, (bf16*)kh, (bf16*)kl,
                                            nullptr, (bf16*)ph, (bf16*)pl, nullptr,
                                            nullptr, nullptr,
                                            NSEQ, NSEQ, EDIM,
                                            (long long)NSEQ * EDIM, (long long)NSEQ * EDIM,
                                            (long long)NSEQ * NSEQ);
    }

    // rowsum over E -> rinv
    rowsum_E<<<MBN, 256>>>((const bf16*)ph, (const bf16*)pl, (float*)rinv);

    // transpose V (hi+lo in one launch via z in [0,8))
    {
        dim3 grid(EDIM / 64, NSEQ / 64, 2 * BATCH);
        transpose_k<<<grid, 256>>>((bf16*)vh, (bf16*)vth, (bf16*)vl, (bf16*)vtl);
    }

    // ctx: C[b] = rinv ⊙ (E[b] @ V[b])
    {
        dim3 grid(EDIM / 256, NSEQ / 128, BATCH);
        gemm_hmma<4><<<grid, 512, SMEM_B>>>((bf16*)ph, (bf16*)pl, (bf16*)vth, (bf16*)vtl,
                                            nullptr, (bf16*)ch, (bf16*)cl, nullptr,
                                            nullptr, (const float*)rinv,
                                            NSEQ, EDIM, NSEQ,
                                            (long long)NSEQ * NSEQ, (long long)EDIM * NSEQ,
                                            (long long)NSEQ * EDIM);
    }

    // out = ctx @ Wo^T + bo
    {
        dim3 grid(DDIM / 256, MBN / 128, 1);
        gemm_hmma<2><<<grid, 512, SMEM_B>>>((bf16*)ch, (bf16*)cl, (bf16*)woh, (bf16*)wol,
                                            out, nullptr, nullptr, bo,
                                            nullptr, nullptr, MBN, DDIM, EDIM, 0, 0, 0);
    }

    (void)in_sizes; (void)n_in; (void)out_size;
}

// round 8
// speedup vs baseline: 1.0385x; 1.0385x over previous
#include <cuda_runtime.h>
#include <cuda_bf16.h>
#include <stdint.h>

#define BATCH 4
#define NSEQ  4096
#define DDIM  1024
#define EDIM  1024

typedef __nv_bfloat16 bf16;

// ---------------- scratch (device globals; no allocations allowed) -------------
__device__ bf16 g_xh[(size_t)BATCH*NSEQ*DDIM], g_xl[(size_t)BATCH*NSEQ*DDIM];
__device__ bf16 g_yh[(size_t)BATCH*NSEQ*DDIM], g_yl[(size_t)BATCH*NSEQ*DDIM];
__device__ bf16 g_wqh[(size_t)EDIM*DDIM], g_wql[(size_t)EDIM*DDIM];
__device__ bf16 g_wkh[(size_t)EDIM*DDIM], g_wkl[(size_t)EDIM*DDIM];
__device__ bf16 g_wvh[(size_t)EDIM*DDIM], g_wvl[(size_t)EDIM*DDIM];
__device__ bf16 g_woh[(size_t)DDIM*EDIM], g_wol[(size_t)DDIM*EDIM];
__device__ bf16 g_qh[(size_t)BATCH*NSEQ*EDIM], g_ql[(size_t)BATCH*NSEQ*EDIM];
__device__ bf16 g_kh[(size_t)BATCH*NSEQ*EDIM], g_kl[(size_t)BATCH*NSEQ*EDIM];
__device__ bf16 g_vh[(size_t)BATCH*NSEQ*EDIM], g_vl[(size_t)BATCH*NSEQ*EDIM];
__device__ bf16 g_vth[(size_t)BATCH*EDIM*NSEQ], g_vtl[(size_t)BATCH*EDIM*NSEQ];
__device__ bf16 g_ph[(size_t)BATCH*NSEQ*NSEQ], g_pl[(size_t)BATCH*NSEQ*NSEQ];
__device__ bf16 g_ch[(size_t)BATCH*NSEQ*EDIM], g_cl[(size_t)BATCH*NSEQ*EDIM];
__device__ float g_spart[(size_t)BATCH*NSEQ*16];
__device__ float g_rinv[(size_t)BATCH*NSEQ];

// ---------------- helpers ----------------
__device__ __forceinline__ uint32_t smem_u32(const void* p) {
    uint32_t a;
    asm("{ .reg .u64 t; cvta.to.shared.u64 t, %1; cvt.u32.u64 %0, t; }" : "=r"(a) : "l"(p));
    return a;
}
__device__ __forceinline__ void cpa16(uint32_t dst, const void* src) {
    asm volatile("cp.async.cg.shared.global [%0], [%1], 16;" :: "r"(dst), "l"(src));
}

#define MMA_BF16(c, a, b) \
    asm volatile("mma.sync.aligned.m16n8k16.row.col.f32.bf16.bf16.f32 " \
                 "{%0,%1,%2,%3},{%4,%5,%6,%7},{%8,%9},{%0,%1,%2,%3};\n" \
                 : "+f"(c[0]), "+f"(c[1]), "+f"(c[2]), "+f"(c[3]) \
                 : "r"(a[0]), "r"(a[1]), "r"(a[2]), "r"(a[3]), "r"(b[0]), "r"(b[1]))

#define LDSM4(r, a) \
    asm volatile("ldmatrix.sync.aligned.m8n8.x4.shared.b16 {%0,%1,%2,%3}, [%4];\n" \
                 : "=r"((r)[0]), "=r"((r)[1]), "=r"((r)[2]), "=r"((r)[3]) : "r"(a))
#define LDSM2(r, a) \
    asm volatile("ldmatrix.sync.aligned.m8n8.x2.shared.b16 {%0,%1}, [%2];\n" \
                 : "=r"((r)[0]), "=r"((r)[1]) : "r"(a))

// ---------------- fp32 -> bf16 hi/lo split (batched over z) ----------------
__device__ __forceinline__ void split_one(const float4* src, bf16* hi, bf16* lo, int i)
{
    float4 v = src[i];
    float vs[4] = {v.x, v.y, v.z, v.w};
    bf16 h[4], l[4];
#pragma unroll
    for (int j = 0; j < 4; j++) {
        h[j] = __float2bfloat16(vs[j]);
        l[j] = __float2bfloat16(vs[j] - __bfloat162float(h[j]));
    }
    __nv_bfloat162 h01; h01.x = h[0]; h01.y = h[1];
    __nv_bfloat162 h23; h23.x = h[2]; h23.y = h[3];
    __nv_bfloat162 l01; l01.x = l[0]; l01.y = l[1];
    __nv_bfloat162 l23; l23.x = l[2]; l23.y = l[3];
    reinterpret_cast<__nv_bfloat162*>(hi)[2*i]   = h01;
    reinterpret_cast<__nv_bfloat162*>(hi)[2*i+1] = h23;
    reinterpret_cast<__nv_bfloat162*>(lo)[2*i]   = l01;
    reinterpret_cast<__nv_bfloat162*>(lo)[2*i+1] = l23;
}

__global__ void split_xy(const float4* __restrict__ x, bf16* xh, bf16* xl,
                         const float4* __restrict__ y, bf16* yh, bf16* yl, int n4)
{
    int i = blockIdx.x * blockDim.x + threadIdx.x;
    if (i >= n4) return;
    if (blockIdx.z == 0) split_one(x, xh, xl, i);
    else                 split_one(y, yh, yl, i);
}

__global__ void split_w(const float4* __restrict__ wq, bf16* wqh, bf16* wql,
                        const float4* __restrict__ wk, bf16* wkh, bf16* wkl,
                        const float4* __restrict__ wv, bf16* wvh, bf16* wvl,
                        const float4* __restrict__ wo, bf16* woh, bf16* wol, int n4)
{
    int i = blockIdx.x * blockDim.x + threadIdx.x;
    if (i >= n4) return;
    switch (blockIdx.z) {
        case 0: split_one(wq, wqh, wql, i); break;
        case 1: split_one(wk, wkh, wkl, i); break;
        case 2: split_one(wv, wvh, wvl, i); break;
        default: split_one(wo, woh, wol, i); break;
    }
}

// ---------------- bf16 transpose per batch: in [NSEQ, EDIM] -> out [EDIM, NSEQ] ---
__global__ __launch_bounds__(256)
void transpose_k(const bf16* __restrict__ in, bf16* __restrict__ out,
                 const bf16* __restrict__ in2, bf16* __restrict__ out2)
{
    __shared__ bf16 t[64][72];
    const int z = blockIdx.z & 3;
    const bf16* src = (blockIdx.z < 4) ? in : in2;
    bf16* dst       = (blockIdx.z < 4) ? out : out2;
    src += (size_t)z * NSEQ * EDIM;
    dst += (size_t)z * EDIM * NSEQ;
    const int x0 = blockIdx.x * 64;
    const int y0 = blockIdx.y * 64;
    const int tid = threadIdx.x;
    const int r = tid >> 3, c = (tid & 7) * 8;
#pragma unroll
    for (int i = 0; i < 2; i++) {
        uint4 v = *(const uint4*)(src + (size_t)(y0 + r + 32*i) * EDIM + x0 + c);
        *(uint4*)&t[r + 32*i][c] = v;
    }
    __syncthreads();
#pragma unroll
    for (int i = 0; i < 2; i++) {
        int orow = r + 32*i;
        bf16 tmp[8];
#pragma unroll
        for (int j = 0; j < 8; j++) tmp[j] = t[c + j][orow];
        *(uint4*)(dst + (size_t)(x0 + orow) * NSEQ + y0 + c) = *(uint4*)tmp;
    }
}

// ---------------- rowsum partials -> 1/sum ----------------
__global__ void rowsum_inv(const float* __restrict__ spart, float* __restrict__ rinv, int nrows)
{
    int r = blockIdx.x * 256 + threadIdx.x;
    if (r >= nrows) return;
    float s = 0.0f;
#pragma unroll
    for (int j = 0; j < 16; j++) s += spart[(size_t)r * 16 + j];
    rinv[r] = 1.0f / s;
}

// ---------------- HMMA split-bf16 GEMM, 256 threads, warp tile 64x64 ----------
// CTA tile 128 (M) x 256 (N), K_TILE=32, 3-stage cp.async, pipelined fragments.
// OUT_MODE: 1 split hi/lo bf16; 2 fp32+bias; 3 exp(acc/32) split + row partials;
//           4 acc*rinv[row] split.

#define NSTAGE   3
#define MAT_A    (128 * 80)
#define MAT_BB   (256 * 80)
#define OFF_AL   (MAT_A)
#define OFF_BH   (2 * MAT_A)
#define STAGE_B  (2 * MAT_A + 2 * MAT_BB)
#define SMEM_B   (NSTAGE * STAGE_B)

template<int OUT_MODE>
__global__ __launch_bounds__(256, 1)
void gemm_hmma(const bf16* __restrict__ Ah, const bf16* __restrict__ Al,
               const bf16* __restrict__ Bh, const bf16* __restrict__ Bl,
               float* __restrict__ outF, bf16* __restrict__ outHi, bf16* __restrict__ outLo,
               const float* __restrict__ bias,
               float* __restrict__ spart, const float* __restrict__ rowscale,
               int M, int N, int K, long long sA, long long sB, long long sC)
{
    extern __shared__ __align__(16) char dsm[];
    __shared__ float part[128][4];
    const uint32_t sb = smem_u32(dsm);

    const int z = blockIdx.z;
    Ah += (size_t)z * sA;  Al += (size_t)z * sA;
    Bh += (size_t)z * sB;  Bl += (size_t)z * sB;

    const int tid = threadIdx.x;
    const int lane = tid & 31;
    const int warp = tid >> 5;
    const int m0 = blockIdx.y * 128;
    const int n0 = blockIdx.x * 256;

    const int wm0 = (warp & 1) * 64;          // 2 warps along M
    const int wn0 = (warp >> 1) * 64;         // 4 warps along N
    const int arow = lane & 15;
    const int acol = (lane >> 4) * 8;
    const int brow = lane & 7;
    const int bcol = ((lane >> 3) & 1) * 8;

    const int nk = K >> 5;

    const int ar0 = tid >> 2,          ac0 = (tid & 3);
    const int ar1 = (tid + 256) >> 2,  ac1 = ((tid + 256) & 3);

    auto load_stage = [&](int kt, int stg) {
        const uint32_t base2 = sb + stg * STAGE_B;
        const int kk = kt << 5;
        {
            uint32_t d = base2 + ar0 * 80 + ac0 * 16;
            const size_t g = (size_t)(m0 + ar0) * K + kk + ac0 * 8;
            cpa16(d,          Ah + g);
            cpa16(d + OFF_AL, Al + g);
        }
        {
            uint32_t d = base2 + ar1 * 80 + ac1 * 16;
            const size_t g = (size_t)(m0 + ar1) * K + kk + ac1 * 8;
            cpa16(d,          Ah + g);
            cpa16(d + OFF_AL, Al + g);
        }
#pragma unroll
        for (int i = 0; i < 4; i++) {
            const int idx = tid + 256 * i;
            const int br = idx >> 2, bc = idx & 3;
            uint32_t d = base2 + OFF_BH + br * 80 + bc * 16;
            const size_t g = (size_t)(n0 + br) * K + kk + bc * 8;
            cpa16(d,           Bh + g);
            cpa16(d + MAT_BB,  Bl + g);
        }
        asm volatile("cp.async.commit_group;" ::: "memory");
    };

    float acc[4][8][4];
#pragma unroll
    for (int t = 0; t < 4; t++)
#pragma unroll
        for (int u = 0; u < 8; u++)
#pragma unroll
            for (int e = 0; e < 4; e++) acc[t][u][e] = 0.0f;

    load_stage(0, 0);
    load_stage(1, 1);

    for (int kt = 0; kt < nk; kt++) {
        asm volatile("cp.async.wait_group 1;" ::: "memory");
        __syncthreads();

        const uint32_t base = sb + (kt % NSTAGE) * STAGE_B;

#pragma unroll
        for (int ks = 0; ks < 2; ks++) {
            const int kbyte = ks * 32;

            // A fragments for this k-step
            uint32_t ah[4][4], al[4][4];
#pragma unroll
            for (int t = 0; t < 4; t++) {
                uint32_t ad = base + (uint32_t)(wm0 + t*16 + arow) * 80 + kbyte + acol * 2;
                LDSM4(ah[t], ad);
                LDSM4(al[t], ad + OFF_AL);
            }

            // B fragments: double-buffered pairs of u (2 columns of 8 at a time)
            uint32_t bh[2][2][2], bl[2][2][2];
#pragma unroll
            for (int uu = 0; uu < 2; uu++) {
                uint32_t bd = base + OFF_BH + (uint32_t)(wn0 + uu*8 + brow) * 80 + kbyte + bcol * 2;
                LDSM2(bh[0][uu], bd);
                LDSM2(bl[0][uu], bd + MAT_BB);
            }

            // issue next-stage global loads AFTER the first fragment burst
            if (ks == 0) {
                if (kt + 2 < nk) load_stage(kt + 2, (kt + 2) % NSTAGE);
                else             asm volatile("cp.async.commit_group;" ::: "memory");
            }

#pragma unroll
            for (int p = 0; p < 4; p++) {
                const int cur = p & 1;
                if (p < 3) {
                    // prefetch next u-pair while current pair computes
#pragma unroll
                    for (int uu = 0; uu < 2; uu++) {
                        uint32_t bd = base + OFF_BH
                                    + (uint32_t)(wn0 + (2*(p+1)+uu)*8 + brow) * 80 + kbyte + bcol * 2;
                        LDSM2(bh[cur^1][uu], bd);
                        LDSM2(bl[cur^1][uu], bd + MAT_BB);
                    }
                }
                // 24 MMAs for this pair (acc reuse distance = 8 MMAs)
#pragma unroll
                for (int uu = 0; uu < 2; uu++)
#pragma unroll
                    for (int t = 0; t < 4; t++) MMA_BF16(acc[t][2*p+uu], ah[t], bh[cur][uu]);
#pragma unroll
                for (int uu = 0; uu < 2; uu++)
#pragma unroll
                    for (int t = 0; t < 4; t++) MMA_BF16(acc[t][2*p+uu], ah[t], bl[cur][uu]);
#pragma unroll
                for (int uu = 0; uu < 2; uu++)
#pragma unroll
                    for (int t = 0; t < 4; t++) MMA_BF16(acc[t][2*p+uu], al[t], bh[cur][uu]);
            }
        }
    }

    // ---- epilogue ----
    const size_t cbase = (size_t)z * sC;
#pragma unroll
    for (int t = 0; t < 4; t++) {
        const int gm = m0 + wm0 + t * 16 + (lane >> 2);
        float rs0 = 0.0f, rs1 = 0.0f;
        float rv0 = 1.0f, rv1 = 1.0f;
        if (OUT_MODE == 4) {
            rv0 = rowscale[(size_t)z * M + gm];
            rv1 = rowscale[(size_t)z * M + gm + 8];
        }
#pragma unroll
        for (int u = 0; u < 8; u++) {
            const int gn = n0 + wn0 + u * 8 + (lane & 3) * 2;
            float v00 = acc[t][u][0], v01 = acc[t][u][1];
            float v10 = acc[t][u][2], v11 = acc[t][u][3];
            if (OUT_MODE == 2) {
                float b0 = bias[gn], b1 = bias[gn + 1];
                v00 += b0; v01 += b1; v10 += b0; v11 += b1;
            }
            if (OUT_MODE == 3) {
                v00 = __expf(v00 * 0.03125f);
                v01 = __expf(v01 * 0.03125f);
                v10 = __expf(v10 * 0.03125f);
                v11 = __expf(v11 * 0.03125f);
                rs0 += v00 + v01;
                rs1 += v10 + v11;
            }
            if (OUT_MODE == 4) {
                v00 *= rv0; v01 *= rv0; v10 *= rv1; v11 *= rv1;
            }
            if (OUT_MODE == 2) {
                *(float2*)(outF + cbase + (size_t)gm * N + gn) = make_float2(v00, v01);
                *(float2*)(outF + cbase + (size_t)(gm + 8) * N + gn) = make_float2(v10, v11);
            } else {
                bf16 h00 = __float2bfloat16(v00), h01 = __float2bfloat16(v01);
                bf16 h10 = __float2bfloat16(v10), h11 = __float2bfloat16(v11);
                __nv_bfloat162 hp0; hp0.x = h00; hp0.y = h01;
                __nv_bfloat162 hp1; hp1.x = h10; hp1.y = h11;
                __nv_bfloat162 lp0; lp0.x = __float2bfloat16(v00 - __bfloat162float(h00));
                                    lp0.y = __float2bfloat16(v01 - __bfloat162float(h01));
                __nv_bfloat162 lp1; lp1.x = __float2bfloat16(v10 - __bfloat162float(h10));
                                    lp1.y = __float2bfloat16(v11 - __bfloat162float(h11));
                *(__nv_bfloat162*)(outHi + cbase + (size_t)gm * N + gn) = hp0;
                *(__nv_bfloat162*)(outHi + cbase + (size_t)(gm + 8) * N + gn) = hp1;
                *(__nv_bfloat162*)(outLo + cbase + (size_t)gm * N + gn) = lp0;
                *(__nv_bfloat162*)(outLo + cbase + (size_t)(gm + 8) * N + gn) = lp1;
            }
        }
        if (OUT_MODE == 3) {
            rs0 += __shfl_xor_sync(0xffffffffu, rs0, 1);
            rs0 += __shfl_xor_sync(0xffffffffu, rs0, 2);
            rs1 += __shfl_xor_sync(0xffffffffu, rs1, 1);
            rs1 += __shfl_xor_sync(0xffffffffu, rs1, 2);
            if ((lane & 3) == 0) {
                part[wm0 + t * 16 + (lane >> 2)][warp >> 1] = rs0;
                part[wm0 + t * 16 + (lane >> 2) + 8][warp >> 1] = rs1;
            }
        }
    }
    if (OUT_MODE == 3) {
        __syncthreads();
        if (tid < 128) {
            float s = part[tid][0] + part[tid][1] + part[tid][2] + part[tid][3];
            spart[((size_t)z * M + m0 + tid) * 16 + blockIdx.x] = s;
        }
    }
}

// ---------------- host ----------------
extern "C" void kernel_launch(void* const* d_in, const int* in_sizes, int n_in,
                              void* d_out, int out_size)
{
    const float* x  = (const float*)d_in[0];
    const float* y  = (const float*)d_in[1];
    const float* Wq = (const float*)d_in[2];
    const float* Wk = (const float*)d_in[3];
    const float* Wv = (const float*)d_in[4];
    const float* Wo = (const float*)d_in[5];
    const float* bo = (const float*)d_in[6];
    float* out = (float*)d_out;

#define GET(sym, var) void* var; cudaGetSymbolAddress(&var, sym)
    GET(g_xh, xh); GET(g_xl, xl); GET(g_yh, yh); GET(g_yl, yl);
    GET(g_wqh, wqh); GET(g_wql, wql); GET(g_wkh, wkh); GET(g_wkl, wkl);
    GET(g_wvh, wvh); GET(g_wvl, wvl); GET(g_woh, woh); GET(g_wol, wol);
    GET(g_qh, qh); GET(g_ql, ql); GET(g_kh, kh); GET(g_kl, kl);
    GET(g_vh, vh); GET(g_vl, vl); GET(g_vth, vth); GET(g_vtl, vtl);
    GET(g_ph, ph); GET(g_pl, pl); GET(g_ch, ch); GET(g_cl, cl);
    GET(g_spart, spart); GET(g_rinv, rinv);
#undef GET

    cudaFuncSetAttribute(gemm_hmma<1>, cudaFuncAttributeMaxDynamicSharedMemorySize, SMEM_B);
    cudaFuncSetAttribute(gemm_hmma<2>, cudaFuncAttributeMaxDynamicSharedMemorySize, SMEM_B);
    cudaFuncSetAttribute(gemm_hmma<3>, cudaFuncAttributeMaxDynamicSharedMemorySize, SMEM_B);
    cudaFuncSetAttribute(gemm_hmma<4>, cudaFuncAttributeMaxDynamicSharedMemorySize, SMEM_B);

    const int MBN = BATCH * NSEQ;            // 16384

    // launches 0-1: splits (batched)
    {
        int n4 = BATCH * NSEQ * DDIM / 4;
        dim3 g1(n4 / 256, 1, 2);
        split_xy<<<g1, 256>>>((const float4*)x, (bf16*)xh, (bf16*)xl,
                              (const float4*)y, (bf16*)yh, (bf16*)yl, n4);
        int w4 = EDIM * DDIM / 4;
        dim3 g2(w4 / 256, 1, 4);
        split_w<<<g2, 256>>>((const float4*)Wq, (bf16*)wqh, (bf16*)wql,
                             (const float4*)Wk, (bf16*)wkh, (bf16*)wkl,
                             (const float4*)Wv, (bf16*)wvh, (bf16*)wvl,
                             (const float4*)Wo, (bf16*)woh, (bf16*)wol, w4);
    }

    // launches 2-4: projections (M=16384, N=1024, K=1024)
    {
        dim3 grid(EDIM / 256, MBN / 128, 1);
        gemm_hmma<1><<<grid, 256, SMEM_B>>>((bf16*)yh, (bf16*)yl, (bf16*)wqh, (bf16*)wql,
                                            nullptr, (bf16*)qh, (bf16*)ql, nullptr,
                                            nullptr, nullptr, MBN, EDIM, DDIM, 0, 0, 0);
        gemm_hmma<1><<<grid, 256, SMEM_B>>>((bf16*)xh, (bf16*)xl, (bf16*)wkh, (bf16*)wkl,
                                            nullptr, (bf16*)kh, (bf16*)kl, nullptr,
                                            nullptr, nullptr, MBN, EDIM, DDIM, 0, 0, 0);
        gemm_hmma<1><<<grid, 256, SMEM_B>>>((bf16*)xh, (bf16*)xl, (bf16*)wvh, (bf16*)wvl,
                                            nullptr, (bf16*)vh, (bf16*)vl, nullptr,
                                            nullptr, nullptr, MBN, EDIM, DDIM, 0, 0, 0);
    }

    // launch 5: scores+exp (ncu -s 5 -c 1 profiles this)
    {
        dim3 grid(NSEQ / 256, NSEQ / 128, BATCH);
        gemm_hmma<3><<<grid, 256, SMEM_B>>>((bf16*)qh, (bf16*)ql, (bf16*)kh, (bf16*)kl,
                                            nullptr, (bf16*)ph, (bf16*)pl, nullptr,
                                            (float*)spart, nullptr,
                                            NSEQ, NSEQ, EDIM,
                                            (long long)NSEQ * EDIM, (long long)NSEQ * EDIM,
                                            (long long)NSEQ * NSEQ);
    }

    // rinv = 1/rowsum from partials
    rowsum_inv<<<MBN / 256, 256>>>((const float*)spart, (float*)rinv, MBN);

    // transpose V (hi+lo in one launch)
    {
        dim3 grid(EDIM / 64, NSEQ / 64, 2 * BATCH);
        transpose_k<<<grid, 256>>>((bf16*)vh, (bf16*)vth, (bf16*)vl, (bf16*)vtl);
    }

    // ctx: C[b] = rinv ⊙ (E[b] @ V[b]) (M=4096, N=1024, K=4096)
    {
        dim3 grid(EDIM / 256, NSEQ / 128, BATCH);
        gemm_hmma<4><<<grid, 256, SMEM_B>>>((bf16*)ph, (bf16*)pl, (bf16*)vth, (bf16*)vtl,
                                            nullptr, (bf16*)ch, (bf16*)cl, nullptr,
                                            nullptr, (const float*)rinv,
                                            NSEQ, EDIM, NSEQ,
                                            (long long)NSEQ * NSEQ, (long long)EDIM * NSEQ,
                                            (long long)NSEQ * EDIM);
    }

    // out = ctx @ Wo^T + bo (M=16384, N=1024, K=1024)
    {
        dim3 grid(DDIM / 256, MBN / 128, 1);
        gemm_hmma<2><<<grid, 256, SMEM_B>>>((bf16*)ch, (bf16*)cl, (bf16*)woh, (bf16*)wol,
                                            out, nullptr, nullptr, bo,
                                            nullptr, nullptr, MBN, DDIM, EDIM, 0, 0, 0);
    }

    (void)in_sizes; (void)n_in; (void)out_size;
}